// round 6
// baseline (speedup 1.0000x reference)
#include <cuda_runtime.h>
#include <math.h>
#include <stdint.h>

// Problem constants
#define NB   4
#define CC   256
#define HH   64
#define WW   64
#define HWSZ 4096        // H*W
#define MTOK 16384       // N*H*W tokens
#define GG   8
#define PP   9
#define CG   32          // C/G
#define NOFF 144         // G*P*2
#define NMSK 72          // G*P
#define NCAT 256         // padded off|mask column count

// Scratch (no allocs allowed)
__device__ float g_c1 [MTOK * CC];    // depthwise conv output, NCHW
__device__ float g_xv [MTOK * CC];    // value proj, NHWC
__device__ float g_x1 [MTOK * CC];    // conv+LN+GELU, NHWC
__device__ float g_om [MTOK * NCAT];  // offset(0..143) | mask logits(144..215) | pad
__device__ float g_y  [MTOK * CC];    // sampled output, NHWC

__device__ __forceinline__ float tf32r(float x) {
    uint32_t u;
    asm("cvt.rna.tf32.f32 %0, %1;" : "=r"(u) : "f"(x));
    return __uint_as_float(u);
}

__device__ __forceinline__ void mma_tf32(float d[4], const uint32_t a[4], const uint32_t b[2]) {
    asm("mma.sync.aligned.m16n8k8.row.col.f32.tf32.tf32.f32 "
        "{%0,%1,%2,%3}, {%4,%5,%6,%7}, {%8,%9}, {%0,%1,%2,%3};"
        : "+f"(d[0]), "+f"(d[1]), "+f"(d[2]), "+f"(d[3])
        : "r"(a[0]), "r"(a[1]), "r"(a[2]), "r"(a[3]), "r"(b[0]), "r"(b[1]));
}

// concat weight gather: [w_off | w_mask | 0]
__device__ __forceinline__ float catw(const float* __restrict__ w_off,
                                      const float* __restrict__ w_mask,
                                      int k, int col) {
    if (col < NOFF) return w_off[k * NOFF + col];
    if (col < NOFF + NMSK) return w_mask[k * NMSK + (col - NOFF)];
    return 0.f;
}

// ---------------------------------------------------------------------------
// TF32 GEMM body: C[M,256] = A[M,256] @ B[256,256] + bias
// ---------------------------------------------------------------------------
#define GBM 128
#define GBN 128
#define GBK 16
#define SPAD 136
#define KTOT 256
#define NKT (KTOT / GBK)
#define SMEM_FLOATS (2 * GBK * SPAD * 2)   // 8704 floats = 34816 B

template<int ATRANS, int BKIND, int STORE_NCHW>
__device__ __forceinline__ void gemm_body(
    const float* __restrict__ A,
    const float* __restrict__ B0, const float* __restrict__ B1,
    const float* __restrict__ bias0, const float* __restrict__ bias1,
    float* __restrict__ Cout, int bx, int by, float* smem)
{
    float (*As)[GBK][SPAD] = (float (*)[GBK][SPAD])smem;
    float (*Bs)[GBK][SPAD] = (float (*)[GBK][SPAD])(smem + 2 * GBK * SPAD);

    int tid  = threadIdx.x;
    int lane = tid & 31;
    int warp = tid >> 5;
    int gid  = lane >> 2;
    int tid4 = lane & 3;
    int wm   = warp >> 1;
    int wn   = warp & 1;
    int m0   = by * GBM;
    int n0   = bx * GBN;

    int ar = tid >> 1;
    int ac = (tid & 1) * 8;
    int br = tid >> 4;
    int bc = (tid & 15) * 8;

    const float* Aptr;
    if (ATRANS) {
        Aptr = A + (size_t)(m0 >> 12) * CC * HWSZ + (size_t)br * HWSZ + (m0 & 4095) + bc;
    } else {
        Aptr = A + (size_t)(m0 + ar) * KTOT + ac;
    }

    float acc[2][8][4];
    #pragma unroll
    for (int i = 0; i < 2; i++)
        #pragma unroll
        for (int j = 0; j < 8; j++)
            #pragma unroll
            for (int q = 0; q < 4; q++) acc[i][j][q] = 0.f;

    float4 pa0, pa1;
    float pv[8];

    pa0 = *(const float4*)(Aptr + 0);
    pa1 = *(const float4*)(Aptr + 4);
    if (BKIND == 2) {
        #pragma unroll
        for (int j = 0; j < 8; j++) pv[j] = catw(B0, B1, br, n0 + bc + j);
    } else {
        float4 b0 = *(const float4*)(B0 + (size_t)br * CC + n0 + bc);
        float4 b1 = *(const float4*)(B0 + (size_t)br * CC + n0 + bc + 4);
        pv[0] = b0.x; pv[1] = b0.y; pv[2] = b0.z; pv[3] = b0.w;
        pv[4] = b1.x; pv[5] = b1.y; pv[6] = b1.z; pv[7] = b1.w;
    }
    if (ATRANS) {
        float4 c0 = make_float4(tf32r(pa0.x), tf32r(pa0.y), tf32r(pa0.z), tf32r(pa0.w));
        float4 c1 = make_float4(tf32r(pa1.x), tf32r(pa1.y), tf32r(pa1.z), tf32r(pa1.w));
        *(float4*)&As[0][br][bc]     = c0;
        *(float4*)&As[0][br][bc + 4] = c1;
    } else {
        As[0][ac + 0][ar] = tf32r(pa0.x); As[0][ac + 1][ar] = tf32r(pa0.y);
        As[0][ac + 2][ar] = tf32r(pa0.z); As[0][ac + 3][ar] = tf32r(pa0.w);
        As[0][ac + 4][ar] = tf32r(pa1.x); As[0][ac + 5][ar] = tf32r(pa1.y);
        As[0][ac + 6][ar] = tf32r(pa1.z); As[0][ac + 7][ar] = tf32r(pa1.w);
    }
    {
        float4 c0 = make_float4(tf32r(pv[0]), tf32r(pv[1]), tf32r(pv[2]), tf32r(pv[3]));
        float4 c1 = make_float4(tf32r(pv[4]), tf32r(pv[5]), tf32r(pv[6]), tf32r(pv[7]));
        *(float4*)&Bs[0][br][bc]     = c0;
        *(float4*)&Bs[0][br][bc + 4] = c1;
    }
    __syncthreads();

    for (int kt = 0; kt < NKT; kt++) {
        int cur = kt & 1;
        if (kt + 1 < NKT) {
            const float* An = ATRANS ? (Aptr + (size_t)(kt + 1) * GBK * HWSZ)
                                     : (Aptr + (kt + 1) * GBK);
            pa0 = *(const float4*)(An + 0);
            pa1 = *(const float4*)(An + 4);
            int kn = (kt + 1) * GBK + br;
            if (BKIND == 2) {
                #pragma unroll
                for (int j = 0; j < 8; j++) pv[j] = catw(B0, B1, kn, n0 + bc + j);
            } else {
                float4 b0 = *(const float4*)(B0 + (size_t)kn * CC + n0 + bc);
                float4 b1 = *(const float4*)(B0 + (size_t)kn * CC + n0 + bc + 4);
                pv[0] = b0.x; pv[1] = b0.y; pv[2] = b0.z; pv[3] = b0.w;
                pv[4] = b1.x; pv[5] = b1.y; pv[6] = b1.z; pv[7] = b1.w;
            }
        }
        #pragma unroll
        for (int ks = 0; ks < 2; ks++) {
            int kk = ks * 8;
            uint32_t af[2][4], bf[8][2];
            #pragma unroll
            for (int mt = 0; mt < 2; mt++) {
                int mb = wm * 32 + mt * 16;
                af[mt][0] = __float_as_uint(As[cur][kk + tid4    ][mb + gid    ]);
                af[mt][1] = __float_as_uint(As[cur][kk + tid4    ][mb + gid + 8]);
                af[mt][2] = __float_as_uint(As[cur][kk + tid4 + 4][mb + gid    ]);
                af[mt][3] = __float_as_uint(As[cur][kk + tid4 + 4][mb + gid + 8]);
            }
            #pragma unroll
            for (int nt = 0; nt < 8; nt++) {
                int nb = wn * 64 + nt * 8;
                bf[nt][0] = __float_as_uint(Bs[cur][kk + tid4    ][nb + gid]);
                bf[nt][1] = __float_as_uint(Bs[cur][kk + tid4 + 4][nb + gid]);
            }
            #pragma unroll
            for (int mt = 0; mt < 2; mt++)
                #pragma unroll
                for (int nt = 0; nt < 8; nt++)
                    mma_tf32(acc[mt][nt], af[mt], bf[nt]);
        }
        if (kt + 1 < NKT) {
            int nxt = cur ^ 1;
            if (ATRANS) {
                float4 c0 = make_float4(tf32r(pa0.x), tf32r(pa0.y), tf32r(pa0.z), tf32r(pa0.w));
                float4 c1 = make_float4(tf32r(pa1.x), tf32r(pa1.y), tf32r(pa1.z), tf32r(pa1.w));
                *(float4*)&As[nxt][br][bc]     = c0;
                *(float4*)&As[nxt][br][bc + 4] = c1;
            } else {
                As[nxt][ac + 0][ar] = tf32r(pa0.x); As[nxt][ac + 1][ar] = tf32r(pa0.y);
                As[nxt][ac + 2][ar] = tf32r(pa0.z); As[nxt][ac + 3][ar] = tf32r(pa0.w);
                As[nxt][ac + 4][ar] = tf32r(pa1.x); As[nxt][ac + 5][ar] = tf32r(pa1.y);
                As[nxt][ac + 6][ar] = tf32r(pa1.z); As[nxt][ac + 7][ar] = tf32r(pa1.w);
            }
            float4 c0 = make_float4(tf32r(pv[0]), tf32r(pv[1]), tf32r(pv[2]), tf32r(pv[3]));
            float4 c1 = make_float4(tf32r(pv[4]), tf32r(pv[5]), tf32r(pv[6]), tf32r(pv[7]));
            *(float4*)&Bs[nxt][br][bc]     = c0;
            *(float4*)&Bs[nxt][br][bc + 4] = c1;
            __syncthreads();
        }
    }

    #pragma unroll
    for (int mt = 0; mt < 2; mt++) {
        int r0 = m0 + wm * 32 + mt * 16 + gid;
        #pragma unroll
        for (int nt = 0; nt < 8; nt++) {
            int cb = n0 + wn * 64 + nt * 8 + 2 * tid4;
            float b0, b1;
            if (BKIND == 2) {
                b0 = (cb < NOFF) ? bias0[cb] : (cb < NOFF + NMSK) ? bias1[cb - NOFF] : 0.f;
                int c1i = cb + 1;
                b1 = (c1i < NOFF) ? bias0[c1i] : (c1i < NOFF + NMSK) ? bias1[c1i - NOFF] : 0.f;
            } else {
                b0 = bias0[cb]; b1 = bias0[cb + 1];
            }
            if (STORE_NCHW) {
                int n0b = r0 >> 12, hw0 = r0 & 4095;
                int n1b = (r0 + 8) >> 12, hw1 = (r0 + 8) & 4095;
                Cout[((size_t)n0b * CC + cb    ) * HWSZ + hw0] = acc[mt][nt][0] + b0;
                Cout[((size_t)n0b * CC + cb + 1) * HWSZ + hw0] = acc[mt][nt][1] + b1;
                Cout[((size_t)n1b * CC + cb    ) * HWSZ + hw1] = acc[mt][nt][2] + b0;
                Cout[((size_t)n1b * CC + cb + 1) * HWSZ + hw1] = acc[mt][nt][3] + b1;
            } else {
                Cout[(size_t)r0 * NCAT + cb]           = acc[mt][nt][0] + b0;
                Cout[(size_t)r0 * NCAT + cb + 1]       = acc[mt][nt][1] + b1;
                Cout[(size_t)(r0 + 8) * NCAT + cb]     = acc[mt][nt][2] + b0;
                Cout[(size_t)(r0 + 8) * NCAT + cb + 1] = acc[mt][nt][3] + b1;
            }
        }
    }
}

// ---------------------------------------------------------------------------
// 1) Fused launch: value-proj GEMM (blocks 0..255) + depthwise conv (rest)
// ---------------------------------------------------------------------------
__global__ void __launch_bounds__(256, 2)
conv_gemm_kernel(const float* __restrict__ in,
                 const float* __restrict__ w_in,
                 const float* __restrict__ b_in,
                 const float* __restrict__ dwk,
                 const float* __restrict__ dwb) {
    __shared__ float smem[SMEM_FLOATS];
    if (blockIdx.x < 256) {
        gemm_body<1, 0, 0>(in, w_in, w_in, b_in, b_in, g_xv,
                           blockIdx.x & 1, blockIdx.x >> 1, smem);
        return;
    }
    float (*sp)[66] = (float (*)[66])smem;
    int b = blockIdx.x - 256;
    int n = b >> 8, c = b & 255;
    int tid = threadIdx.x;

    for (int i = tid; i < 66 * 66; i += 256) ((float*)sp)[i] = 0.f;
    __syncthreads();

    const float* src = in + ((size_t)n * CC + c) * HWSZ;
    for (int i = tid; i < HWSZ; i += 256) {
        int h = i >> 6, w = i & 63;
        sp[h + 1][w + 1] = src[i];
    }
    __syncthreads();

    float k00 = dwk[0 * CC + c], k01 = dwk[1 * CC + c], k02 = dwk[2 * CC + c];
    float k10 = dwk[3 * CC + c], k11 = dwk[4 * CC + c], k12 = dwk[5 * CC + c];
    float k20 = dwk[6 * CC + c], k21 = dwk[7 * CC + c], k22 = dwk[8 * CC + c];
    float bb  = dwb[c];

    float* dst = g_c1 + ((size_t)n * CC + c) * HWSZ;
    for (int i = tid; i < HWSZ; i += 256) {
        int h = i >> 6, w = i & 63;
        float acc = bb;
        acc = fmaf(sp[h    ][w    ], k00, acc);
        acc = fmaf(sp[h    ][w + 1], k01, acc);
        acc = fmaf(sp[h    ][w + 2], k02, acc);
        acc = fmaf(sp[h + 1][w    ], k10, acc);
        acc = fmaf(sp[h + 1][w + 1], k11, acc);
        acc = fmaf(sp[h + 1][w + 2], k12, acc);
        acc = fmaf(sp[h + 2][w    ], k20, acc);
        acc = fmaf(sp[h + 2][w + 1], k21, acc);
        acc = fmaf(sp[h + 2][w + 2], k22, acc);
        dst[i] = acc;
    }
}

__global__ void __launch_bounds__(256, 2)
gemm_om_kernel(const float* __restrict__ A, const float* __restrict__ w_off,
               const float* __restrict__ w_mask, const float* __restrict__ b_off,
               const float* __restrict__ b_mask, float* __restrict__ Cout) {
    __shared__ float smem[SMEM_FLOATS];
    gemm_body<0, 2, 0>(A, w_off, w_mask, b_off, b_mask, Cout,
                       blockIdx.x & 1, blockIdx.x >> 1, smem);
}

__global__ void __launch_bounds__(256, 2)
gemm_out_kernel(const float* __restrict__ A, const float* __restrict__ B,
                const float* __restrict__ bias, float* __restrict__ Cout) {
    __shared__ float smem[SMEM_FLOATS];
    gemm_body<0, 0, 1>(A, B, B, bias, bias, Cout,
                       blockIdx.x & 1, blockIdx.x >> 1, smem);
}

// ---------------------------------------------------------------------------
// 2) LayerNorm + exact GELU with NCHW -> NHWC transpose.
// ---------------------------------------------------------------------------
__global__ void __launch_bounds__(256)
ln_gelu_kernel(const float* __restrict__ lng, const float* __restrict__ lnb) {
    __shared__ float tile[256][33];
    __shared__ float smu[32], srs[32];

    int tid = threadIdx.x;
    int t0 = blockIdx.x * 32;
    int n = t0 >> 12, hw0 = t0 & 4095;

    const float* src = g_c1 + (size_t)n * CC * HWSZ + hw0;
    int tx = tid & 31, ty = tid >> 5;
    #pragma unroll 4
    for (int cc = 0; cc < 32; cc++) {
        int ch = cc * 8 + ty;
        tile[ch][tx] = src[(size_t)ch * HWSZ + tx];
    }
    __syncthreads();

    int tok = tid >> 3, thr = tid & 7;
    float s1 = 0.f, s2 = 0.f;
    #pragma unroll 8
    for (int i = 0; i < 32; i++) {
        float v = tile[thr + 8 * i][tok];
        s1 += v; s2 += v * v;
    }
    #pragma unroll
    for (int d = 1; d < 8; d <<= 1) {
        s1 += __shfl_xor_sync(0xffffffffu, s1, d);
        s2 += __shfl_xor_sync(0xffffffffu, s2, d);
    }
    if (thr == 0) {
        float mu = s1 * (1.0f / 256.0f);
        float var = s2 * (1.0f / 256.0f) - mu * mu;
        smu[tok] = mu;
        srs[tok] = rsqrtf(var + 1e-6f);
    }
    __syncthreads();

    float gma = lng[tid], bta = lnb[tid];
    #pragma unroll 4
    for (int j = 0; j < 32; j++) {
        float v = (tile[tid][j] - smu[j]) * srs[j] * gma + bta;
        v = 0.5f * v * (1.0f + erff(v * 0.70710678118654752f));
        g_x1[(size_t)(t0 + j) * CC + tid] = v;
    }
}

// ---------------------------------------------------------------------------
// 5+6) DCNv3 sampling, two-phase, 2 tokens/thread for MLP.
// Block = 8 tokens, 256 threads.
// Phase 1a: 64 (token,group) pairs -> softmax max + inv-sum.
// Phase 1b: 576 (pair,p) tasks -> weights (validity folded) + clamped indices.
// Phase 2:  thread = (g, l8, tokenhalf); handles tokens half and half+4:
//           per p, 4 broadcast LDS + 8 unconditional LDG.128 + 32 FMA,
//           two independent load streams.
// ---------------------------------------------------------------------------
__global__ void __launch_bounds__(256)
dcn_kernel() {
    __shared__ float4 swt[64][9];
    __shared__ int4   sit[64][9];
    __shared__ float  smx[64], sinv[64];

    int tid  = threadIdx.x;
    int tblk = blockIdx.x * 8;

    // ---- phase 1a: per-pair softmax stats ----
    if (tid < 64) {
        int tl = tid >> 3, g = tid & 7;
        int t = tblk + tl;
        const float* lgp = g_om + (size_t)t * NCAT + NOFF + g * PP;
        float mx = lgp[0];
        #pragma unroll
        for (int j = 1; j < PP; j++) mx = fmaxf(mx, lgp[j]);
        float s = 0.f;
        #pragma unroll
        for (int j = 0; j < PP; j++) s += __expf(lgp[j] - mx);
        smx[tid]  = mx;
        sinv[tid] = 1.0f / s;
    }
    __syncthreads();

    // ---- phase 1b: weights + indices ----
    for (int task = tid; task < 64 * PP; task += 256) {
        int pair = task / PP;
        int p    = task - pair * PP;
        int tl   = pair >> 3, g = pair & 7;
        int t    = tblk + tl;
        int hw = t & 4095, h = hw >> 6, w = hw & 63;

        const float* base = g_om + (size_t)t * NCAT;
        float m = __expf(base[NOFF + g * PP + p] - smx[pair]) * sinv[pair];

        float ox = base[g * (PP * 2) + 2 * p];
        float oy = base[g * (PP * 2) + 2 * p + 1];
        float kx = (float)(p / 3 - 1);
        float ky = (float)(p % 3 - 1);
        float px = (float)w + 1.0f + 2.0f * (kx + ox);
        float py = (float)h + 1.0f + 2.0f * (ky + oy);
        float x0f = floorf(px), y0f = floorf(py);
        float wx = px - x0f, wy = py - y0f;
        int x0 = (int)x0f, y0 = (int)y0f;

        bool bx0 = (x0 >= 1) & (x0 <= WW);
        bool bx1 = (x0 >= 0) & (x0 <= WW - 1);
        bool by0 = (y0 >= 1) & (y0 <= HH);
        bool by1 = (y0 >= 0) & (y0 <= HH - 1);

        int ix0 = min(max(x0 - 1, 0), WW - 1);
        int ix1 = min(max(x0,     0), WW - 1);
        int iy0 = min(max(y0 - 1, 0), HH - 1);
        int iy1 = min(max(y0,     0), HH - 1);

        float4 wv;
        wv.x = (bx0 & by0) ? m * (1.f - wx) * (1.f - wy) : 0.f;
        wv.y = (bx1 & by0) ? m * wx * (1.f - wy)         : 0.f;
        wv.z = (bx0 & by1) ? m * (1.f - wx) * wy         : 0.f;
        wv.w = (bx1 & by1) ? m * wx * wy                 : 0.f;
        swt[pair][p] = wv;
        sit[pair][p] = make_int4(iy0 * WW + ix0, iy0 * WW + ix1,
                                 iy1 * WW + ix0, iy1 * WW + ix1);
    }
    __syncthreads();

    // ---- phase 2: dual-stream gather ----
    int l8   = tid & 7;
    int g    = (tid >> 3) & 7;
    int half = tid >> 6;               // 0..3
    int t0   = tblk + half;
    int t1   = tblk + 4 + half;
    int p0   = (half << 3) | g;        // pair for t0
    int p1   = ((half + 4) << 3) | g;  // pair for t1

    const float4* xb0 = (const float4*)(g_xv + (size_t)(t0 >> 12) * HWSZ * CC + g * CG) + l8;
    const float4* xb1 = (const float4*)(g_xv + (size_t)(t1 >> 12) * HWSZ * CC + g * CG) + l8;

    float a0x = 0.f, a0y = 0.f, a0z = 0.f, a0w = 0.f;
    float a1x = 0.f, a1y = 0.f, a1z = 0.f, a1w = 0.f;
    #pragma unroll
    for (int p = 0; p < PP; p++) {
        float4 w0 = swt[p0][p];
        int4   i0 = sit[p0][p];
        float4 w1 = swt[p1][p];
        int4   i1 = sit[p1][p];

        float4 u00 = xb0[(size_t)i0.x * (CC / 4)];
        float4 u01 = xb0[(size_t)i0.y * (CC / 4)];
        float4 u10 = xb0[(size_t)i0.z * (CC / 4)];
        float4 u11 = xb0[(size_t)i0.w * (CC / 4)];
        float4 v00 = xb1[(size_t)i1.x * (CC / 4)];
        float4 v01 = xb1[(size_t)i1.y * (CC / 4)];
        float4 v10 = xb1[(size_t)i1.z * (CC / 4)];
        float4 v11 = xb1[(size_t)i1.w * (CC / 4)];

        a0x = fmaf(w0.x, u00.x, fmaf(w0.y, u01.x, fmaf(w0.z, u10.x, fmaf(w0.w, u11.x, a0x))));
        a0y = fmaf(w0.x, u00.y, fmaf(w0.y, u01.y, fmaf(w0.z, u10.y, fmaf(w0.w, u11.y, a0y))));
        a0z = fmaf(w0.x, u00.z, fmaf(w0.y, u01.z, fmaf(w0.z, u10.z, fmaf(w0.w, u11.z, a0z))));
        a0w = fmaf(w0.x, u00.w, fmaf(w0.y, u01.w, fmaf(w0.z, u10.w, fmaf(w0.w, u11.w, a0w))));
        a1x = fmaf(w1.x, v00.x, fmaf(w1.y, v01.x, fmaf(w1.z, v10.x, fmaf(w1.w, v11.x, a1x))));
        a1y = fmaf(w1.x, v00.y, fmaf(w1.y, v01.y, fmaf(w1.z, v10.y, fmaf(w1.w, v11.y, a1y))));
        a1z = fmaf(w1.x, v00.z, fmaf(w1.y, v01.z, fmaf(w1.z, v10.z, fmaf(w1.w, v11.z, a1z))));
        a1w = fmaf(w1.x, v00.w, fmaf(w1.y, v01.w, fmaf(w1.z, v10.w, fmaf(w1.w, v11.w, a1w))));
    }
    ((float4*)(g_y + (size_t)t0 * CC + g * CG))[l8] = make_float4(a0x, a0y, a0z, a0w);
    ((float4*)(g_y + (size_t)t1 * CC + g * CG))[l8] = make_float4(a1x, a1y, a1z, a1w);
}

// ---------------------------------------------------------------------------
extern "C" void kernel_launch(void* const* d_in, const int* in_sizes, int n_in,
                              void* d_out, int out_size) {
    const float* inputs = (const float*)d_in[0];
    const float* w_in   = (const float*)d_in[1];
    const float* b_in   = (const float*)d_in[2];
    const float* dw_k   = (const float*)d_in[3];
    const float* dw_b   = (const float*)d_in[4];
    const float* ln_g   = (const float*)d_in[5];
    const float* ln_b   = (const float*)d_in[6];
    const float* w_off  = (const float*)d_in[7];
    const float* b_off  = (const float*)d_in[8];
    const float* w_mask = (const float*)d_in[9];
    const float* b_mask = (const float*)d_in[10];
    const float* w_out  = (const float*)d_in[11];
    const float* b_out  = (const float*)d_in[12];
    float* out = (float*)d_out;

    static float *p_x1 = nullptr, *p_om = nullptr, *p_y = nullptr;
    if (!p_x1) {
        cudaGetSymbolAddress((void**)&p_x1, g_x1);
        cudaGetSymbolAddress((void**)&p_om, g_om);
        cudaGetSymbolAddress((void**)&p_y,  g_y);
    }

    // 1) fused: value-proj GEMM + depthwise conv
    conv_gemm_kernel<<<256 + NB * CC, 256>>>(inputs, w_in, b_in, dw_k, dw_b);
    // 2) LayerNorm + GELU + transpose to NHWC
    ln_gelu_kernel<<<MTOK / 32, 256>>>(ln_g, ln_b);
    // 3) offset + mask logits (concat B staged in-kernel)
    gemm_om_kernel<<<256, 256>>>(p_x1, w_off, w_mask, b_off, b_mask, p_om);
    // 4) softmax + deformable sampling (two-phase, dual stream)
    dcn_kernel<<<MTOK / 8, 256>>>();
    // 5) output projection, NCHW store
    gemm_out_kernel<<<256, 256>>>(p_y, w_out, b_out, out);
}

// round 8
// speedup vs baseline: 1.4995x; 1.4995x over previous
#include <cuda_runtime.h>
#include <math.h>
#include <stdint.h>

// Problem constants
#define NB   4
#define CC   256
#define HH   64
#define WW   64
#define HWSZ 4096        // H*W
#define MTOK 16384       // N*H*W tokens
#define GG   8
#define PP   9
#define CG   32          // C/G
#define NOFF 144         // G*P*2
#define NMSK 72          // G*P
#define NCAT 256         // padded off|mask column count

// Scratch (no allocs allowed)
__device__ float g_c1 [MTOK * CC];    // depthwise conv output, NCHW
__device__ float g_xv [MTOK * CC];    // value proj, NHWC
__device__ float g_om [MTOK * NCAT];  // offset(0..143) | mask logits(144..215) | pad
__device__ float g_y  [MTOK * CC];    // sampled output, NHWC
__device__ float g_mu [MTOK];         // LN mean per token
__device__ float g_rs [MTOK];         // LN rsqrt(var+eps) per token

__device__ __forceinline__ float tf32r(float x) {
    uint32_t u;
    asm("cvt.rna.tf32.f32 %0, %1;" : "=r"(u) : "f"(x));
    return __uint_as_float(u);
}

__device__ __forceinline__ float gelu_exact(float v) {
    return 0.5f * v * (1.0f + erff(v * 0.70710678118654752f));
}

__device__ __forceinline__ void mma_tf32(float d[4], const uint32_t a[4], const uint32_t b[2]) {
    asm("mma.sync.aligned.m16n8k8.row.col.f32.tf32.tf32.f32 "
        "{%0,%1,%2,%3}, {%4,%5,%6,%7}, {%8,%9}, {%0,%1,%2,%3};"
        : "+f"(d[0]), "+f"(d[1]), "+f"(d[2]), "+f"(d[3])
        : "r"(a[0]), "r"(a[1]), "r"(a[2]), "r"(a[3]), "r"(b[0]), "r"(b[1]));
}

// concat weight gather: [w_off | w_mask | 0]
__device__ __forceinline__ float catw(const float* __restrict__ w_off,
                                      const float* __restrict__ w_mask,
                                      int k, int col) {
    if (col < NOFF) return w_off[k * NOFF + col];
    if (col < NOFF + NMSK) return w_mask[k * NMSK + (col - NOFF)];
    return 0.f;
}

// ---------------------------------------------------------------------------
// TF32 GEMM body: C[M,256] = A[M,256] @ B[256,256] + bias
// ATRANS=0: A row-major [M,K]. ATRANS=1: A from NCHW (per-n column-major).
// ATRANS=2: like 1 but from g_c1 with fused LayerNorm+GELU (mu/rs per col,
//           gamma/beta per k) applied at staging.
// BKIND=0: plain B. BKIND=2: concat [w_off|w_mask|0].
// STORE_NCHW=1: store to NCHW [4][256][4096].
// ---------------------------------------------------------------------------
#define GBM 128
#define GBN 128
#define GBK 16
#define SPAD 136
#define KTOT 256
#define NKT (KTOT / GBK)
#define SMEM_FLOATS (2 * GBK * SPAD * 2)   // 8704 floats = 34816 B

template<int ATRANS, int BKIND, int STORE_NCHW>
__device__ __forceinline__ void gemm_body(
    const float* __restrict__ A,
    const float* __restrict__ B0, const float* __restrict__ B1,
    const float* __restrict__ bias0, const float* __restrict__ bias1,
    const float* __restrict__ lng, const float* __restrict__ lnb,
    float* __restrict__ Cout, int bx, int by, float* smem)
{
    float (*As)[GBK][SPAD] = (float (*)[GBK][SPAD])smem;
    float (*Bs)[GBK][SPAD] = (float (*)[GBK][SPAD])(smem + 2 * GBK * SPAD);

    int tid  = threadIdx.x;
    int lane = tid & 31;
    int warp = tid >> 5;
    int gid  = lane >> 2;
    int tid4 = lane & 3;
    int wm   = warp >> 1;
    int wn   = warp & 1;
    int m0   = by * GBM;
    int n0   = bx * GBN;

    int ar = tid >> 1;
    int ac = (tid & 1) * 8;
    int br = tid >> 4;
    int bc = (tid & 15) * 8;

    const float* Aptr;
    if (ATRANS) {
        Aptr = A + (size_t)(m0 >> 12) * CC * HWSZ + (size_t)br * HWSZ + (m0 & 4095) + bc;
    } else {
        Aptr = A + (size_t)(m0 + ar) * KTOT + ac;
    }

    // LN per-column stats (token = m0+bc..+7), invariant over k
    float mu[8], rs[8];
    if (ATRANS == 2) {
        float4 m04 = *(const float4*)(g_mu + m0 + bc);
        float4 m14 = *(const float4*)(g_mu + m0 + bc + 4);
        float4 r04 = *(const float4*)(g_rs + m0 + bc);
        float4 r14 = *(const float4*)(g_rs + m0 + bc + 4);
        mu[0] = m04.x; mu[1] = m04.y; mu[2] = m04.z; mu[3] = m04.w;
        mu[4] = m14.x; mu[5] = m14.y; mu[6] = m14.z; mu[7] = m14.w;
        rs[0] = r04.x; rs[1] = r04.y; rs[2] = r04.z; rs[3] = r04.w;
        rs[4] = r14.x; rs[5] = r14.y; rs[6] = r14.z; rs[7] = r14.w;
    }

    float acc[2][8][4];
    #pragma unroll
    for (int i = 0; i < 2; i++)
        #pragma unroll
        for (int j = 0; j < 8; j++)
            #pragma unroll
            for (int q = 0; q < 4; q++) acc[i][j][q] = 0.f;

    float4 pa0, pa1;
    float pv[8];
    float pgk = 0.f, pbk = 0.f;

    // prologue: k-tile 0
    pa0 = *(const float4*)(Aptr + 0);
    pa1 = *(const float4*)(Aptr + 4);
    if (ATRANS == 2) { pgk = lng[br]; pbk = lnb[br]; }
    if (BKIND == 2) {
        #pragma unroll
        for (int j = 0; j < 8; j++) pv[j] = catw(B0, B1, br, n0 + bc + j);
    } else {
        float4 b0 = *(const float4*)(B0 + (size_t)br * CC + n0 + bc);
        float4 b1 = *(const float4*)(B0 + (size_t)br * CC + n0 + bc + 4);
        pv[0] = b0.x; pv[1] = b0.y; pv[2] = b0.z; pv[3] = b0.w;
        pv[4] = b1.x; pv[5] = b1.y; pv[6] = b1.z; pv[7] = b1.w;
    }
    {
        float av[8] = {pa0.x, pa0.y, pa0.z, pa0.w, pa1.x, pa1.y, pa1.z, pa1.w};
        if (ATRANS == 2) {
            #pragma unroll
            for (int j = 0; j < 8; j++)
                av[j] = gelu_exact((av[j] - mu[j]) * rs[j] * pgk + pbk);
        }
        if (ATRANS) {
            #pragma unroll
            for (int j = 0; j < 8; j++) As[0][br][bc + j] = tf32r(av[j]);
        } else {
            #pragma unroll
            for (int j = 0; j < 8; j++) As[0][ac + j][ar] = tf32r(av[j]);
        }
    }
    {
        float4 c0 = make_float4(tf32r(pv[0]), tf32r(pv[1]), tf32r(pv[2]), tf32r(pv[3]));
        float4 c1 = make_float4(tf32r(pv[4]), tf32r(pv[5]), tf32r(pv[6]), tf32r(pv[7]));
        *(float4*)&Bs[0][br][bc]     = c0;
        *(float4*)&Bs[0][br][bc + 4] = c1;
    }
    __syncthreads();

    for (int kt = 0; kt < NKT; kt++) {
        int cur = kt & 1;
        if (kt + 1 < NKT) {
            const float* An = ATRANS ? (Aptr + (size_t)(kt + 1) * GBK * HWSZ)
                                     : (Aptr + (kt + 1) * GBK);
            pa0 = *(const float4*)(An + 0);
            pa1 = *(const float4*)(An + 4);
            int kn = (kt + 1) * GBK + br;
            if (ATRANS == 2) { pgk = lng[kn]; pbk = lnb[kn]; }
            if (BKIND == 2) {
                #pragma unroll
                for (int j = 0; j < 8; j++) pv[j] = catw(B0, B1, kn, n0 + bc + j);
            } else {
                float4 b0 = *(const float4*)(B0 + (size_t)kn * CC + n0 + bc);
                float4 b1 = *(const float4*)(B0 + (size_t)kn * CC + n0 + bc + 4);
                pv[0] = b0.x; pv[1] = b0.y; pv[2] = b0.z; pv[3] = b0.w;
                pv[4] = b1.x; pv[5] = b1.y; pv[6] = b1.z; pv[7] = b1.w;
            }
        }
        #pragma unroll
        for (int ks = 0; ks < 2; ks++) {
            int kk = ks * 8;
            uint32_t af[2][4], bf[8][2];
            #pragma unroll
            for (int mt = 0; mt < 2; mt++) {
                int mb = wm * 32 + mt * 16;
                af[mt][0] = __float_as_uint(As[cur][kk + tid4    ][mb + gid    ]);
                af[mt][1] = __float_as_uint(As[cur][kk + tid4    ][mb + gid + 8]);
                af[mt][2] = __float_as_uint(As[cur][kk + tid4 + 4][mb + gid    ]);
                af[mt][3] = __float_as_uint(As[cur][kk + tid4 + 4][mb + gid + 8]);
            }
            #pragma unroll
            for (int nt = 0; nt < 8; nt++) {
                int nb = wn * 64 + nt * 8;
                bf[nt][0] = __float_as_uint(Bs[cur][kk + tid4    ][nb + gid]);
                bf[nt][1] = __float_as_uint(Bs[cur][kk + tid4 + 4][nb + gid]);
            }
            #pragma unroll
            for (int mt = 0; mt < 2; mt++)
                #pragma unroll
                for (int nt = 0; nt < 8; nt++)
                    mma_tf32(acc[mt][nt], af[mt], bf[nt]);
        }
        if (kt + 1 < NKT) {
            int nxt = cur ^ 1;
            float av[8] = {pa0.x, pa0.y, pa0.z, pa0.w, pa1.x, pa1.y, pa1.z, pa1.w};
            if (ATRANS == 2) {
                #pragma unroll
                for (int j = 0; j < 8; j++)
                    av[j] = gelu_exact((av[j] - mu[j]) * rs[j] * pgk + pbk);
            }
            if (ATRANS) {
                #pragma unroll
                for (int j = 0; j < 8; j++) As[nxt][br][bc + j] = tf32r(av[j]);
            } else {
                #pragma unroll
                for (int j = 0; j < 8; j++) As[nxt][ac + j][ar] = tf32r(av[j]);
            }
            float4 c0 = make_float4(tf32r(pv[0]), tf32r(pv[1]), tf32r(pv[2]), tf32r(pv[3]));
            float4 c1 = make_float4(tf32r(pv[4]), tf32r(pv[5]), tf32r(pv[6]), tf32r(pv[7]));
            *(float4*)&Bs[nxt][br][bc]     = c0;
            *(float4*)&Bs[nxt][br][bc + 4] = c1;
            __syncthreads();
        }
    }

    #pragma unroll
    for (int mt = 0; mt < 2; mt++) {
        int r0 = m0 + wm * 32 + mt * 16 + gid;
        #pragma unroll
        for (int nt = 0; nt < 8; nt++) {
            int cb = n0 + wn * 64 + nt * 8 + 2 * tid4;
            float b0, b1;
            if (BKIND == 2) {
                b0 = (cb < NOFF) ? bias0[cb] : (cb < NOFF + NMSK) ? bias1[cb - NOFF] : 0.f;
                int c1i = cb + 1;
                b1 = (c1i < NOFF) ? bias0[c1i] : (c1i < NOFF + NMSK) ? bias1[c1i - NOFF] : 0.f;
            } else {
                b0 = bias0[cb]; b1 = bias0[cb + 1];
            }
            if (STORE_NCHW) {
                int n0b = r0 >> 12, hw0 = r0 & 4095;
                int n1b = (r0 + 8) >> 12, hw1 = (r0 + 8) & 4095;
                Cout[((size_t)n0b * CC + cb    ) * HWSZ + hw0] = acc[mt][nt][0] + b0;
                Cout[((size_t)n0b * CC + cb + 1) * HWSZ + hw0] = acc[mt][nt][1] + b1;
                Cout[((size_t)n1b * CC + cb    ) * HWSZ + hw1] = acc[mt][nt][2] + b0;
                Cout[((size_t)n1b * CC + cb + 1) * HWSZ + hw1] = acc[mt][nt][3] + b1;
            } else {
                Cout[(size_t)r0 * NCAT + cb]           = acc[mt][nt][0] + b0;
                Cout[(size_t)r0 * NCAT + cb + 1]       = acc[mt][nt][1] + b1;
                Cout[(size_t)(r0 + 8) * NCAT + cb]     = acc[mt][nt][2] + b0;
                Cout[(size_t)(r0 + 8) * NCAT + cb + 1] = acc[mt][nt][3] + b1;
            }
        }
    }
}

// ---------------------------------------------------------------------------
// 1) Fused launch: value-proj GEMM (blocks 0..255) + depthwise conv (rest)
// ---------------------------------------------------------------------------
__global__ void __launch_bounds__(256, 2)
conv_gemm_kernel(const float* __restrict__ in,
                 const float* __restrict__ w_in,
                 const float* __restrict__ b_in,
                 const float* __restrict__ dwk,
                 const float* __restrict__ dwb) {
    __shared__ float smem[SMEM_FLOATS];
    if (blockIdx.x < 256) {
        gemm_body<1, 0, 0>(in, w_in, w_in, b_in, b_in, b_in, b_in, g_xv,
                           blockIdx.x & 1, blockIdx.x >> 1, smem);
        return;
    }
    float (*sp)[66] = (float (*)[66])smem;
    int b = blockIdx.x - 256;
    int n = b >> 8, c = b & 255;
    int tid = threadIdx.x;

    for (int i = tid; i < 66 * 66; i += 256) ((float*)sp)[i] = 0.f;
    __syncthreads();

    const float* src = in + ((size_t)n * CC + c) * HWSZ;
    for (int i = tid; i < HWSZ; i += 256) {
        int h = i >> 6, w = i & 63;
        sp[h + 1][w + 1] = src[i];
    }
    __syncthreads();

    float k00 = dwk[0 * CC + c], k01 = dwk[1 * CC + c], k02 = dwk[2 * CC + c];
    float k10 = dwk[3 * CC + c], k11 = dwk[4 * CC + c], k12 = dwk[5 * CC + c];
    float k20 = dwk[6 * CC + c], k21 = dwk[7 * CC + c], k22 = dwk[8 * CC + c];
    float bb  = dwb[c];

    float* dst = g_c1 + ((size_t)n * CC + c) * HWSZ;
    for (int i = tid; i < HWSZ; i += 256) {
        int h = i >> 6, w = i & 63;
        float acc = bb;
        acc = fmaf(sp[h    ][w    ], k00, acc);
        acc = fmaf(sp[h    ][w + 1], k01, acc);
        acc = fmaf(sp[h    ][w + 2], k02, acc);
        acc = fmaf(sp[h + 1][w    ], k10, acc);
        acc = fmaf(sp[h + 1][w + 1], k11, acc);
        acc = fmaf(sp[h + 1][w + 2], k12, acc);
        acc = fmaf(sp[h + 2][w    ], k20, acc);
        acc = fmaf(sp[h + 2][w + 1], k21, acc);
        acc = fmaf(sp[h + 2][w + 2], k22, acc);
        dst[i] = acc;
    }
}

// om GEMM: A from g_c1 with fused LN+GELU; B = concat [w_off|w_mask|0]
__global__ void __launch_bounds__(256, 2)
gemm_om_kernel(const float* __restrict__ w_off, const float* __restrict__ w_mask,
               const float* __restrict__ b_off, const float* __restrict__ b_mask,
               const float* __restrict__ lng, const float* __restrict__ lnb,
               float* __restrict__ Cout) {
    __shared__ float smem[SMEM_FLOATS];
    gemm_body<2, 2, 0>(g_c1, w_off, w_mask, b_off, b_mask, lng, lnb, Cout,
                       blockIdx.x & 1, blockIdx.x >> 1, smem);
}

__global__ void __launch_bounds__(256, 2)
gemm_out_kernel(const float* __restrict__ A, const float* __restrict__ B,
                const float* __restrict__ bias, float* __restrict__ Cout) {
    __shared__ float smem[SMEM_FLOATS];
    gemm_body<0, 0, 1>(A, B, B, bias, bias, bias, bias, Cout,
                       blockIdx.x & 1, blockIdx.x >> 1, smem);
}

// ---------------------------------------------------------------------------
// 2) LN stats only: per-token mean + rsqrt(var+eps) from NCHW conv output.
// ---------------------------------------------------------------------------
__global__ void __launch_bounds__(256)
ln_stats_kernel() {
    __shared__ float tile[256][33];

    int tid = threadIdx.x;
    int t0 = blockIdx.x * 32;
    int n = t0 >> 12, hw0 = t0 & 4095;

    const float* src = g_c1 + (size_t)n * CC * HWSZ + hw0;
    int tx = tid & 31, ty = tid >> 5;
    #pragma unroll 4
    for (int cc = 0; cc < 32; cc++) {
        int ch = cc * 8 + ty;
        tile[ch][tx] = src[(size_t)ch * HWSZ + tx];
    }
    __syncthreads();

    int tok = tid >> 3, thr = tid & 7;
    float s1 = 0.f, s2 = 0.f;
    #pragma unroll 8
    for (int i = 0; i < 32; i++) {
        float v = tile[thr + 8 * i][tok];
        s1 += v; s2 += v * v;
    }
    #pragma unroll
    for (int d = 1; d < 8; d <<= 1) {
        s1 += __shfl_xor_sync(0xffffffffu, s1, d);
        s2 += __shfl_xor_sync(0xffffffffu, s2, d);
    }
    if (thr == 0) {
        float mu = s1 * (1.0f / 256.0f);
        float var = s2 * (1.0f / 256.0f) - mu * mu;
        g_mu[t0 + tok] = mu;
        g_rs[t0 + tok] = rsqrtf(var + 1e-6f);
    }
}

// ---------------------------------------------------------------------------
// 5+6) DCNv3 sampling, two-phase (R4 proven version). Block = 4 tokens.
// ---------------------------------------------------------------------------
__global__ void __launch_bounds__(256)
dcn_kernel() {
    __shared__ float4 swt[32][9];
    __shared__ int4   sit[32][9];

    int tid  = threadIdx.x;
    int tblk = blockIdx.x * 4;

    for (int task = tid; task < 32 * PP; task += 256) {
        int pair = task / PP;
        int p    = task - pair * PP;
        int tl   = pair >> 3, g = pair & 7;
        int t    = tblk + tl;
        int hw = t & 4095, h = hw >> 6, w = hw & 63;

        const float* base = g_om + (size_t)t * NCAT;
        const float* lgp  = base + NOFF + g * PP;

        float mx = lgp[0];
        #pragma unroll
        for (int j = 1; j < PP; j++) mx = fmaxf(mx, lgp[j]);
        float s = 0.f, ep = 0.f;
        #pragma unroll
        for (int j = 0; j < PP; j++) {
            float e = __expf(lgp[j] - mx);
            s += e;
            if (j == p) ep = e;
        }
        float m = ep / s;

        float ox = base[g * (PP * 2) + 2 * p];
        float oy = base[g * (PP * 2) + 2 * p + 1];
        float kx = (float)(p / 3 - 1);
        float ky = (float)(p % 3 - 1);
        float px = (float)w + 1.0f + 2.0f * (kx + ox);
        float py = (float)h + 1.0f + 2.0f * (ky + oy);
        float x0f = floorf(px), y0f = floorf(py);
        float wx = px - x0f, wy = py - y0f;
        int x0 = (int)x0f, y0 = (int)y0f;

        bool bx0 = (x0 >= 1) & (x0 <= WW);
        bool bx1 = (x0 >= 0) & (x0 <= WW - 1);
        bool by0 = (y0 >= 1) & (y0 <= HH);
        bool by1 = (y0 >= 0) & (y0 <= HH - 1);

        int ix0 = min(max(x0 - 1, 0), WW - 1);
        int ix1 = min(max(x0,     0), WW - 1);
        int iy0 = min(max(y0 - 1, 0), HH - 1);
        int iy1 = min(max(y0,     0), HH - 1);

        float4 wv;
        wv.x = (bx0 & by0) ? m * (1.f - wx) * (1.f - wy) : 0.f;
        wv.y = (bx1 & by0) ? m * wx * (1.f - wy)         : 0.f;
        wv.z = (bx0 & by1) ? m * (1.f - wx) * wy         : 0.f;
        wv.w = (bx1 & by1) ? m * wx * wy                 : 0.f;
        swt[pair][p] = wv;
        sit[pair][p] = make_int4(iy0 * WW + ix0, iy0 * WW + ix1,
                                 iy1 * WW + ix0, iy1 * WW + ix1);
    }
    __syncthreads();

    int tl   = tid >> 6;
    int sub  = tid & 63;
    int g    = sub >> 3, l8 = sub & 7;
    int pair = (tl << 3) | g;
    int t    = tblk + tl;
    int n    = t >> 12;

    const float4* xvb = (const float4*)(g_xv + (size_t)n * HWSZ * CC + g * CG) + l8;

    float ax = 0.f, ay = 0.f, az = 0.f, aw = 0.f;
    #pragma unroll
    for (int p = 0; p < PP; p++) {
        float4 wv = swt[pair][p];
        int4   iv = sit[pair][p];
        float4 v00 = xvb[(size_t)iv.x * (CC / 4)];
        float4 v01 = xvb[(size_t)iv.y * (CC / 4)];
        float4 v10 = xvb[(size_t)iv.z * (CC / 4)];
        float4 v11 = xvb[(size_t)iv.w * (CC / 4)];
        ax = fmaf(wv.x, v00.x, fmaf(wv.y, v01.x, fmaf(wv.z, v10.x, fmaf(wv.w, v11.x, ax))));
        ay = fmaf(wv.x, v00.y, fmaf(wv.y, v01.y, fmaf(wv.z, v10.y, fmaf(wv.w, v11.y, ay))));
        az = fmaf(wv.x, v00.z, fmaf(wv.y, v01.z, fmaf(wv.z, v10.z, fmaf(wv.w, v11.z, az))));
        aw = fmaf(wv.x, v00.w, fmaf(wv.y, v01.w, fmaf(wv.z, v10.w, fmaf(wv.w, v11.w, aw))));
    }
    ((float4*)(g_y + (size_t)t * CC + g * CG))[l8] = make_float4(ax, ay, az, aw);
}

// ---------------------------------------------------------------------------
extern "C" void kernel_launch(void* const* d_in, const int* in_sizes, int n_in,
                              void* d_out, int out_size) {
    const float* inputs = (const float*)d_in[0];
    const float* w_in   = (const float*)d_in[1];
    const float* b_in   = (const float*)d_in[2];
    const float* dw_k   = (const float*)d_in[3];
    const float* dw_b   = (const float*)d_in[4];
    const float* ln_g   = (const float*)d_in[5];
    const float* ln_b   = (const float*)d_in[6];
    const float* w_off  = (const float*)d_in[7];
    const float* b_off  = (const float*)d_in[8];
    const float* w_mask = (const float*)d_in[9];
    const float* b_mask = (const float*)d_in[10];
    const float* w_out  = (const float*)d_in[11];
    const float* b_out  = (const float*)d_in[12];
    float* out = (float*)d_out;

    static float *p_om = nullptr, *p_y = nullptr;
    if (!p_om) {
        cudaGetSymbolAddress((void**)&p_om, g_om);
        cudaGetSymbolAddress((void**)&p_y,  g_y);
    }

    // 1) fused: value-proj GEMM + depthwise conv
    conv_gemm_kernel<<<256 + NB * CC, 256>>>(inputs, w_in, b_in, dw_k, dw_b);
    // 2) LN stats (mean + rsig per token)
    ln_stats_kernel<<<MTOK / 32, 256>>>();
    // 3) offset + mask logits; LN+GELU fused into A staging
    gemm_om_kernel<<<256, 256>>>(w_off, w_mask, b_off, b_mask, ln_g, ln_b, p_om);
    // 4) softmax + deformable sampling
    dcn_kernel<<<MTOK / 4, 256>>>();
    // 5) output projection, NCHW store
    gemm_out_kernel<<<256, 256>>>(p_y, w_out, b_out, out);
}

// round 11
// speedup vs baseline: 1.5321x; 1.0218x over previous
#include <cuda_runtime.h>
#include <math.h>
#include <stdint.h>

// Problem constants
#define NB   4
#define CC   256
#define HH   64
#define WW   64
#define HWSZ 4096        // H*W
#define MTOK 16384       // N*H*W tokens
#define GG   8
#define PP   9
#define CG   32          // C/G
#define NOFF 144         // G*P*2
#define NMSK 72          // G*P
#define NCAT 256         // padded off|mask column count

// Scratch (no allocs allowed)
__device__ float g_c1 [MTOK * CC];    // depthwise conv output, NCHW
__device__ float g_xv [MTOK * CC];    // value proj, NHWC
__device__ float g_om [MTOK * NCAT];  // offset(0..143) | mask logits(144..215) | pad
__device__ float g_y  [MTOK * CC];    // sampled output, NHWC
__device__ float g_mu [MTOK];         // LN mean per token
__device__ float g_rs [MTOK];         // LN rsqrt(var+eps) per token

__device__ __forceinline__ float tf32r(float x) {
    uint32_t u;
    asm("cvt.rna.tf32.f32 %0, %1;" : "=r"(u) : "f"(x));
    return __uint_as_float(u);
}

__device__ __forceinline__ float gelu_exact(float v) {
    return 0.5f * v * (1.0f + erff(v * 0.70710678118654752f));
}

__device__ __forceinline__ void mma_tf32(float d[4], const uint32_t a[4], const uint32_t b[2]) {
    asm("mma.sync.aligned.m16n8k8.row.col.f32.tf32.tf32.f32 "
        "{%0,%1,%2,%3}, {%4,%5,%6,%7}, {%8,%9}, {%0,%1,%2,%3};"
        : "+f"(d[0]), "+f"(d[1]), "+f"(d[2]), "+f"(d[3])
        : "r"(a[0]), "r"(a[1]), "r"(a[2]), "r"(a[3]), "r"(b[0]), "r"(b[1]));
}

// concat weight gather: [w_off | w_mask | 0]
__device__ __forceinline__ float catw(const float* __restrict__ w_off,
                                      const float* __restrict__ w_mask,
                                      int k, int col) {
    if (col < NOFF) return w_off[k * NOFF + col];
    if (col < NOFF + NMSK) return w_mask[k * NMSK + (col - NOFF)];
    return 0.f;
}

// ---------------------------------------------------------------------------
// TF32 GEMM body: C[M,256] = A[M,256] @ B[256,256] + bias
// ATRANS=0: A row-major [M,K]. ATRANS=1: A from NCHW (per-n column-major).
// ATRANS=2: like 1 but from g_c1 with fused LayerNorm+GELU applied at staging.
// BKIND=0: plain B. BKIND=2: concat [w_off|w_mask|0].
// STORE_NCHW=1: store to NCHW [4][256][4096].
// ---------------------------------------------------------------------------
#define GBM 128
#define GBN 128
#define GBK 16
#define SPAD 136
#define KTOT 256
#define NKT (KTOT / GBK)
#define SMEM_FLOATS (2 * GBK * SPAD * 2)   // 8704 floats = 34816 B

template<int ATRANS, int BKIND, int STORE_NCHW>
__device__ __forceinline__ void gemm_body(
    const float* __restrict__ A,
    const float* __restrict__ B0, const float* __restrict__ B1,
    const float* __restrict__ bias0, const float* __restrict__ bias1,
    const float* __restrict__ lng, const float* __restrict__ lnb,
    float* __restrict__ Cout, int bx, int by, float* smem)
{
    float (*As)[GBK][SPAD] = (float (*)[GBK][SPAD])smem;
    float (*Bs)[GBK][SPAD] = (float (*)[GBK][SPAD])(smem + 2 * GBK * SPAD);

    int tid  = threadIdx.x;
    int lane = tid & 31;
    int warp = tid >> 5;
    int gid  = lane >> 2;
    int tid4 = lane & 3;
    int wm   = warp >> 1;
    int wn   = warp & 1;
    int m0   = by * GBM;
    int n0   = bx * GBN;

    int ar = tid >> 1;
    int ac = (tid & 1) * 8;
    int br = tid >> 4;
    int bc = (tid & 15) * 8;

    const float* Aptr;
    if (ATRANS) {
        Aptr = A + (size_t)(m0 >> 12) * CC * HWSZ + (size_t)br * HWSZ + (m0 & 4095) + bc;
    } else {
        Aptr = A + (size_t)(m0 + ar) * KTOT + ac;
    }

    // LN per-column stats (token = m0+bc..+7), invariant over k
    float mu[8], rs[8];
    if (ATRANS == 2) {
        float4 m04 = *(const float4*)(g_mu + m0 + bc);
        float4 m14 = *(const float4*)(g_mu + m0 + bc + 4);
        float4 r04 = *(const float4*)(g_rs + m0 + bc);
        float4 r14 = *(const float4*)(g_rs + m0 + bc + 4);
        mu[0] = m04.x; mu[1] = m04.y; mu[2] = m04.z; mu[3] = m04.w;
        mu[4] = m14.x; mu[5] = m14.y; mu[6] = m14.z; mu[7] = m14.w;
        rs[0] = r04.x; rs[1] = r04.y; rs[2] = r04.z; rs[3] = r04.w;
        rs[4] = r14.x; rs[5] = r14.y; rs[6] = r14.z; rs[7] = r14.w;
    }

    float acc[2][8][4];
    #pragma unroll
    for (int i = 0; i < 2; i++)
        #pragma unroll
        for (int j = 0; j < 8; j++)
            #pragma unroll
            for (int q = 0; q < 4; q++) acc[i][j][q] = 0.f;

    float4 pa0, pa1;
    float pv[8];
    float pgk = 0.f, pbk = 0.f;

    // prologue: k-tile 0
    pa0 = *(const float4*)(Aptr + 0);
    pa1 = *(const float4*)(Aptr + 4);
    if (ATRANS == 2) { pgk = lng[br]; pbk = lnb[br]; }
    if (BKIND == 2) {
        #pragma unroll
        for (int j = 0; j < 8; j++) pv[j] = catw(B0, B1, br, n0 + bc + j);
    } else {
        float4 b0 = *(const float4*)(B0 + (size_t)br * CC + n0 + bc);
        float4 b1 = *(const float4*)(B0 + (size_t)br * CC + n0 + bc + 4);
        pv[0] = b0.x; pv[1] = b0.y; pv[2] = b0.z; pv[3] = b0.w;
        pv[4] = b1.x; pv[5] = b1.y; pv[6] = b1.z; pv[7] = b1.w;
    }
    {
        float av[8] = {pa0.x, pa0.y, pa0.z, pa0.w, pa1.x, pa1.y, pa1.z, pa1.w};
        if (ATRANS == 2) {
            #pragma unroll
            for (int j = 0; j < 8; j++)
                av[j] = gelu_exact((av[j] - mu[j]) * rs[j] * pgk + pbk);
        }
        if (ATRANS) {
            #pragma unroll
            for (int j = 0; j < 8; j++) As[0][br][bc + j] = tf32r(av[j]);
        } else {
            #pragma unroll
            for (int j = 0; j < 8; j++) As[0][ac + j][ar] = tf32r(av[j]);
        }
    }
    {
        float4 c0 = make_float4(tf32r(pv[0]), tf32r(pv[1]), tf32r(pv[2]), tf32r(pv[3]));
        float4 c1 = make_float4(tf32r(pv[4]), tf32r(pv[5]), tf32r(pv[6]), tf32r(pv[7]));
        *(float4*)&Bs[0][br][bc]     = c0;
        *(float4*)&Bs[0][br][bc + 4] = c1;
    }
    __syncthreads();

    for (int kt = 0; kt < NKT; kt++) {
        int cur = kt & 1;
        if (kt + 1 < NKT) {
            const float* An = ATRANS ? (Aptr + (size_t)(kt + 1) * GBK * HWSZ)
                                     : (Aptr + (kt + 1) * GBK);
            pa0 = *(const float4*)(An + 0);
            pa1 = *(const float4*)(An + 4);
            int kn = (kt + 1) * GBK + br;
            if (ATRANS == 2) { pgk = lng[kn]; pbk = lnb[kn]; }
            if (BKIND == 2) {
                #pragma unroll
                for (int j = 0; j < 8; j++) pv[j] = catw(B0, B1, kn, n0 + bc + j);
            } else {
                float4 b0 = *(const float4*)(B0 + (size_t)kn * CC + n0 + bc);
                float4 b1 = *(const float4*)(B0 + (size_t)kn * CC + n0 + bc + 4);
                pv[0] = b0.x; pv[1] = b0.y; pv[2] = b0.z; pv[3] = b0.w;
                pv[4] = b1.x; pv[5] = b1.y; pv[6] = b1.z; pv[7] = b1.w;
            }
        }
        #pragma unroll
        for (int ks = 0; ks < 2; ks++) {
            int kk = ks * 8;
            uint32_t af[2][4], bf[8][2];
            #pragma unroll
            for (int mt = 0; mt < 2; mt++) {
                int mb = wm * 32 + mt * 16;
                af[mt][0] = __float_as_uint(As[cur][kk + tid4    ][mb + gid    ]);
                af[mt][1] = __float_as_uint(As[cur][kk + tid4    ][mb + gid + 8]);
                af[mt][2] = __float_as_uint(As[cur][kk + tid4 + 4][mb + gid    ]);
                af[mt][3] = __float_as_uint(As[cur][kk + tid4 + 4][mb + gid + 8]);
            }
            #pragma unroll
            for (int nt = 0; nt < 8; nt++) {
                int nb = wn * 64 + nt * 8;
                bf[nt][0] = __float_as_uint(Bs[cur][kk + tid4    ][nb + gid]);
                bf[nt][1] = __float_as_uint(Bs[cur][kk + tid4 + 4][nb + gid]);
            }
            #pragma unroll
            for (int mt = 0; mt < 2; mt++)
                #pragma unroll
                for (int nt = 0; nt < 8; nt++)
                    mma_tf32(acc[mt][nt], af[mt], bf[nt]);
        }
        if (kt + 1 < NKT) {
            int nxt = cur ^ 1;
            float av[8] = {pa0.x, pa0.y, pa0.z, pa0.w, pa1.x, pa1.y, pa1.z, pa1.w};
            if (ATRANS == 2) {
                #pragma unroll
                for (int j = 0; j < 8; j++)
                    av[j] = gelu_exact((av[j] - mu[j]) * rs[j] * pgk + pbk);
            }
            if (ATRANS) {
                #pragma unroll
                for (int j = 0; j < 8; j++) As[nxt][br][bc + j] = tf32r(av[j]);
            } else {
                #pragma unroll
                for (int j = 0; j < 8; j++) As[nxt][ac + j][ar] = tf32r(av[j]);
            }
            float4 c0 = make_float4(tf32r(pv[0]), tf32r(pv[1]), tf32r(pv[2]), tf32r(pv[3]));
            float4 c1 = make_float4(tf32r(pv[4]), tf32r(pv[5]), tf32r(pv[6]), tf32r(pv[7]));
            *(float4*)&Bs[nxt][br][bc]     = c0;
            *(float4*)&Bs[nxt][br][bc + 4] = c1;
            __syncthreads();
        }
    }

    #pragma unroll
    for (int mt = 0; mt < 2; mt++) {
        int r0 = m0 + wm * 32 + mt * 16 + gid;
        #pragma unroll
        for (int nt = 0; nt < 8; nt++) {
            int cb = n0 + wn * 64 + nt * 8 + 2 * tid4;
            float b0, b1;
            if (BKIND == 2) {
                b0 = (cb < NOFF) ? bias0[cb] : (cb < NOFF + NMSK) ? bias1[cb - NOFF] : 0.f;
                int c1i = cb + 1;
                b1 = (c1i < NOFF) ? bias0[c1i] : (c1i < NOFF + NMSK) ? bias1[c1i - NOFF] : 0.f;
            } else {
                b0 = bias0[cb]; b1 = bias0[cb + 1];
            }
            if (STORE_NCHW) {
                int n0b = r0 >> 12, hw0 = r0 & 4095;
                int n1b = (r0 + 8) >> 12, hw1 = (r0 + 8) & 4095;
                Cout[((size_t)n0b * CC + cb    ) * HWSZ + hw0] = acc[mt][nt][0] + b0;
                Cout[((size_t)n0b * CC + cb + 1) * HWSZ + hw0] = acc[mt][nt][1] + b1;
                Cout[((size_t)n1b * CC + cb    ) * HWSZ + hw1] = acc[mt][nt][2] + b0;
                Cout[((size_t)n1b * CC + cb + 1) * HWSZ + hw1] = acc[mt][nt][3] + b1;
            } else {
                Cout[(size_t)r0 * NCAT + cb]           = acc[mt][nt][0] + b0;
                Cout[(size_t)r0 * NCAT + cb + 1]       = acc[mt][nt][1] + b1;
                Cout[(size_t)(r0 + 8) * NCAT + cb]     = acc[mt][nt][2] + b0;
                Cout[(size_t)(r0 + 8) * NCAT + cb + 1] = acc[mt][nt][3] + b1;
            }
        }
    }
}

// ---------------------------------------------------------------------------
// 1) Fused launch: value-proj GEMM (blocks 0..255) + depthwise conv (rest)
// ---------------------------------------------------------------------------
__global__ void __launch_bounds__(256, 2)
conv_gemm_kernel(const float* __restrict__ in,
                 const float* __restrict__ w_in,
                 const float* __restrict__ b_in,
                 const float* __restrict__ dwk,
                 const float* __restrict__ dwb) {
    __shared__ float smem[SMEM_FLOATS];
    if (blockIdx.x < 256) {
        gemm_body<1, 0, 0>(in, w_in, w_in, b_in, b_in, b_in, b_in, g_xv,
                           blockIdx.x & 1, blockIdx.x >> 1, smem);
        return;
    }
    float (*sp)[66] = (float (*)[66])smem;
    int b = blockIdx.x - 256;
    int n = b >> 8, c = b & 255;
    int tid = threadIdx.x;

    for (int i = tid; i < 66 * 66; i += 256) ((float*)sp)[i] = 0.f;
    __syncthreads();

    const float* src = in + ((size_t)n * CC + c) * HWSZ;
    for (int i = tid; i < HWSZ; i += 256) {
        int h = i >> 6, w = i & 63;
        sp[h + 1][w + 1] = src[i];
    }
    __syncthreads();

    float k00 = dwk[0 * CC + c], k01 = dwk[1 * CC + c], k02 = dwk[2 * CC + c];
    float k10 = dwk[3 * CC + c], k11 = dwk[4 * CC + c], k12 = dwk[5 * CC + c];
    float k20 = dwk[6 * CC + c], k21 = dwk[7 * CC + c], k22 = dwk[8 * CC + c];
    float bb  = dwb[c];

    float* dst = g_c1 + ((size_t)n * CC + c) * HWSZ;
    for (int i = tid; i < HWSZ; i += 256) {
        int h = i >> 6, w = i & 63;
        float acc = bb;
        acc = fmaf(sp[h    ][w    ], k00, acc);
        acc = fmaf(sp[h    ][w + 1], k01, acc);
        acc = fmaf(sp[h    ][w + 2], k02, acc);
        acc = fmaf(sp[h + 1][w    ], k10, acc);
        acc = fmaf(sp[h + 1][w + 1], k11, acc);
        acc = fmaf(sp[h + 1][w + 2], k12, acc);
        acc = fmaf(sp[h + 2][w    ], k20, acc);
        acc = fmaf(sp[h + 2][w + 1], k21, acc);
        acc = fmaf(sp[h + 2][w + 2], k22, acc);
        dst[i] = acc;
    }
}

// om GEMM: A from g_c1 with fused LN+GELU; B = concat [w_off|w_mask|0]
__global__ void __launch_bounds__(256, 2)
gemm_om_kernel(const float* __restrict__ w_off, const float* __restrict__ w_mask,
               const float* __restrict__ b_off, const float* __restrict__ b_mask,
               const float* __restrict__ lng, const float* __restrict__ lnb,
               float* __restrict__ Cout) {
    __shared__ float smem[SMEM_FLOATS];
    gemm_body<2, 2, 0>(g_c1, w_off, w_mask, b_off, b_mask, lng, lnb, Cout,
                       blockIdx.x & 1, blockIdx.x >> 1, smem);
}

__global__ void __launch_bounds__(256, 2)
gemm_out_kernel(const float* __restrict__ A, const float* __restrict__ B,
                const float* __restrict__ bias, float* __restrict__ Cout) {
    __shared__ float smem[SMEM_FLOATS];
    gemm_body<0, 0, 1>(A, B, B, bias, bias, bias, bias, Cout,
                       blockIdx.x & 1, blockIdx.x >> 1, smem);
}

// ---------------------------------------------------------------------------
// 2) LN stats only: per-token mean + rsqrt(var+eps) from NCHW conv output.
// ---------------------------------------------------------------------------
__global__ void __launch_bounds__(256)
ln_stats_kernel() {
    __shared__ float tile[256][33];

    int tid = threadIdx.x;
    int t0 = blockIdx.x * 32;
    int n = t0 >> 12, hw0 = t0 & 4095;

    const float* src = g_c1 + (size_t)n * CC * HWSZ + hw0;
    int tx = tid & 31, ty = tid >> 5;
    #pragma unroll 4
    for (int cc = 0; cc < 32; cc++) {
        int ch = cc * 8 + ty;
        tile[ch][tx] = src[(size_t)ch * HWSZ + tx];
    }
    __syncthreads();

    int tok = tid >> 3, thr = tid & 7;
    float s1 = 0.f, s2 = 0.f;
    #pragma unroll 8
    for (int i = 0; i < 32; i++) {
        float v = tile[thr + 8 * i][tok];
        s1 += v; s2 += v * v;
    }
    #pragma unroll
    for (int d = 1; d < 8; d <<= 1) {
        s1 += __shfl_xor_sync(0xffffffffu, s1, d);
        s2 += __shfl_xor_sync(0xffffffffu, s2, d);
    }
    if (thr == 0) {
        float mu = s1 * (1.0f / 256.0f);
        float var = s2 * (1.0f / 256.0f) - mu * mu;
        g_mu[t0 + tok] = mu;
        g_rs[t0 + tok] = rsqrtf(var + 1e-6f);
    }
}

// ---------------------------------------------------------------------------
// 5+6) DCNv3 sampling + fused softmax — R4 one-phase form (measured 39.3us).
//      8 lanes x float4 per group; block = 4 tokens x 64 threads.
//      Per-thread redundant softmax; predicated unguarded-index loads.
// ---------------------------------------------------------------------------
__global__ void __launch_bounds__(256)
dcn_kernel() {
    int tid = threadIdx.x;
    int t   = blockIdx.x * 4 + (tid >> 6);
    int sub = tid & 63;
    int g   = sub >> 3, l8 = sub & 7;
    int n = t >> 12, hw = t & 4095, h = hw >> 6, w = hw & 63;

    const float* off = g_om + (size_t)t * NCAT + g * (PP * 2);
    const float* lg  = g_om + (size_t)t * NCAT + NOFF + g * PP;
    const float4* xvb = (const float4*)(g_xv + (size_t)n * HWSZ * CC + g * CG) + l8;
    // pixel stride in float4 units: CC/4 = 64

    float e[PP];
    float mx = lg[0];
    #pragma unroll
    for (int p = 1; p < PP; p++) mx = fmaxf(mx, lg[p]);
    float s = 0.f;
    #pragma unroll
    for (int p = 0; p < PP; p++) { e[p] = __expf(lg[p] - mx); s += e[p]; }
    float inv = 1.0f / s;

    float ax = 0.f, ay = 0.f, az = 0.f, aw = 0.f;
    #pragma unroll
    for (int p = 0; p < PP; p++) {
        float kx = (float)(p / 3 - 1);
        float ky = (float)(p % 3 - 1);
        float px = (float)w + 1.0f + 2.0f * (kx + off[p * 2 + 0]);
        float py = (float)h + 1.0f + 2.0f * (ky + off[p * 2 + 1]);
        float x0f = floorf(px), y0f = floorf(py);
        float wx = px - x0f, wy = py - y0f;
        int x0 = (int)x0f, y0 = (int)y0f;
        float m = e[p] * inv;

        bool bx0 = (x0 >= 1) & (x0 <= WW);
        bool bx1 = (x0 >= 0) & (x0 <= WW - 1);
        bool by0 = (y0 >= 1) & (y0 <= HH);
        bool by1 = (y0 >= 0) & (y0 <= HH - 1);

        float4 v00 = {0,0,0,0}, v01 = {0,0,0,0}, v10 = {0,0,0,0}, v11 = {0,0,0,0};
        if (bx0 & by0) v00 = xvb[(size_t)((y0 - 1) * WW + (x0 - 1)) * (CC / 4)];
        if (bx1 & by0) v01 = xvb[(size_t)((y0 - 1) * WW + x0) * (CC / 4)];
        if (bx0 & by1) v10 = xvb[(size_t)(y0 * WW + (x0 - 1)) * (CC / 4)];
        if (bx1 & by1) v11 = xvb[(size_t)(y0 * WW + x0) * (CC / 4)];

        float w00 = m * (1.f - wx) * (1.f - wy);
        float w01 = m * wx * (1.f - wy);
        float w10 = m * (1.f - wx) * wy;
        float w11 = m * wx * wy;

        ax = fmaf(w00, v00.x, fmaf(w01, v01.x, fmaf(w10, v10.x, fmaf(w11, v11.x, ax))));
        ay = fmaf(w00, v00.y, fmaf(w01, v01.y, fmaf(w10, v10.y, fmaf(w11, v11.y, ay))));
        az = fmaf(w00, v00.z, fmaf(w01, v01.z, fmaf(w10, v10.z, fmaf(w11, v11.z, az))));
        aw = fmaf(w00, v00.w, fmaf(w01, v01.w, fmaf(w10, v10.w, fmaf(w11, v11.w, aw))));
    }
    ((float4*)(g_y + (size_t)t * CC + g * CG))[l8] = make_float4(ax, ay, az, aw);
}

// ---------------------------------------------------------------------------
extern "C" void kernel_launch(void* const* d_in, const int* in_sizes, int n_in,
                              void* d_out, int out_size) {
    const float* inputs = (const float*)d_in[0];
    const float* w_in   = (const float*)d_in[1];
    const float* b_in   = (const float*)d_in[2];
    const float* dw_k   = (const float*)d_in[3];
    const float* dw_b   = (const float*)d_in[4];
    const float* ln_g   = (const float*)d_in[5];
    const float* ln_b   = (const float*)d_in[6];
    const float* w_off  = (const float*)d_in[7];
    const float* b_off  = (const float*)d_in[8];
    const float* w_mask = (const float*)d_in[9];
    const float* b_mask = (const float*)d_in[10];
    const float* w_out  = (const float*)d_in[11];
    const float* b_out  = (const float*)d_in[12];
    float* out = (float*)d_out;

    static float *p_om = nullptr, *p_y = nullptr;
    if (!p_om) {
        cudaGetSymbolAddress((void**)&p_om, g_om);
        cudaGetSymbolAddress((void**)&p_y,  g_y);
    }

    // 1) fused: value-proj GEMM + depthwise conv
    conv_gemm_kernel<<<256 + NB * CC, 256>>>(inputs, w_in, b_in, dw_k, dw_b);
    // 2) LN stats (mean + rsig per token)
    ln_stats_kernel<<<MTOK / 32, 256>>>();
    // 3) offset + mask logits; LN+GELU fused into A staging
    gemm_om_kernel<<<256, 256>>>(w_off, w_mask, b_off, b_mask, ln_g, ln_b, p_om);
    // 4) softmax + deformable sampling (one-phase, R4 form)
    dcn_kernel<<<MTOK / 4, 256>>>();
    // 5) output projection, NCHW store
    gemm_out_kernel<<<256, 256>>>(p_y, w_out, b_out, out);
}